// round 1
// baseline (speedup 1.0000x reference)
#include <cuda_runtime.h>
#include <math.h>

#define N_NODES 100000
#define D 128
#define K_HOPS 2
#define FAN_IN (D * (K_HOPS + 1))   // 384

// ---- scratch (no allocations allowed; __device__ globals) ----
__device__ float g_norm[N_NODES];
__device__ float g_h1[N_NODES * D];
__device__ float g_h2[N_NODES * D];
__device__ float g_Wt[FAN_IN * D];   // W transposed: Wt[k][o]
__device__ int   g_idx64;            // 1 if src/dst are int64, 0 if int32

// ---------------------------------------------------------------------------
// dtype probe: reference guarantees dst[0..N-1] == arange(N).
// int64 little-endian viewed as int32: [0,0,1,0,2,0,...]; int32: [0,1,2,...]
__global__ void detect_idx_kernel(const int* dst32) {
    if (threadIdx.x == 0 && blockIdx.x == 0) {
        g_idx64 = (dst32[1] == 0 && dst32[2] == 1 && dst32[4] == 2) ? 1 : 0;
    }
}

__device__ __forceinline__ int load_idx(const int* p, int e, int is64) {
    return is64 ? p[2 * e] : p[e];
}

// ---------------------------------------------------------------------------
__global__ void zero_kernel(float* p, int n) {
    int i = blockIdx.x * blockDim.x + threadIdx.x;
    if (i < n) p[i] = 0.0f;
}

__global__ void deg_kernel(const int* dst32, int E) {
    int e = blockIdx.x * blockDim.x + threadIdx.x;
    if (e < E) {
        int t = load_idx(dst32, e, g_idx64);
        atomicAdd(&g_norm[t], 1.0f);
    }
}

__global__ void rsqrt_kernel() {
    int i = blockIdx.x * blockDim.x + threadIdx.x;
    if (i < N_NODES) g_norm[i] = rsqrtf(g_norm[i]);
}

// W is [D_OUT=128][FAN_IN=384] row-major; build Wt[k][o] = W[o][k]
__global__ void transpose_w_kernel(const float* __restrict__ W) {
    int idx = blockIdx.x * blockDim.x + threadIdx.x;   // over 128*384
    if (idx < D * FAN_IN) {
        int o = idx / FAN_IN;
        int k = idx % FAN_IN;
        g_Wt[k * D + o] = W[idx];
    }
}

// scatter: hout[dst] += hin[src] * norm[src]   (2 edges per 256-thread block)
__global__ void scatter_kernel(const float* __restrict__ hin,
                               float* __restrict__ hout,
                               const int* __restrict__ src32,
                               const int* __restrict__ dst32, int E) {
    int e = blockIdx.x * 2 + (threadIdx.x >> 7);
    int d = threadIdx.x & 127;
    if (e >= E) return;
    int is64 = g_idx64;
    int s = load_idx(src32, e, is64);
    int t = load_idx(dst32, e, is64);
    float v = __ldg(&hin[s * D + d]) * g_norm[s];
    atomicAdd(&hout[t * D + d], v);
}

__global__ void scale_kernel(float* __restrict__ h) {
    int i = blockIdx.x * blockDim.x + threadIdx.x;
    if (i < N_NODES * D) h[i] *= g_norm[i >> 7];
}

// ---------------------------------------------------------------------------
// SGEMM: out[n][o] = b[o] + sum_k x[n][k] * Wt[k][o]
// x is the virtual concat [feat | h1 | h2].
// BM=128, BN=128(=full N), BK=8, 256 threads, 8x8 microtile.
#define BM 128
#define BN 128
#define BK 8
#define TM 8
#define TN 8

__global__ __launch_bounds__(256)
void gemm_kernel(const float* __restrict__ feat,
                 const float* __restrict__ bias,
                 float* __restrict__ out) {
    __shared__ float As[BK][BM];
    __shared__ float Bs[BK][BN];

    int rowBase = blockIdx.x * BM;
    int tid = threadIdx.x;
    int tr = tid / 16;        // 0..15
    int tc = tid % 16;        // 0..15

    float acc[TM][TN];
#pragma unroll
    for (int i = 0; i < TM; i++)
#pragma unroll
        for (int j = 0; j < TN; j++) acc[i][j] = 0.0f;

    for (int k0 = 0; k0 < FAN_IN; k0 += BK) {
        // load A tile (BM x BK), 4 elems/thread
#pragma unroll
        for (int i = 0; i < 4; i++) {
            int idx = tid + i * 256;
            int r = idx >> 3;
            int c = idx & 7;
            int grow = rowBase + r;
            int k = k0 + c;
            const float* base = (k < 128) ? feat : ((k < 256) ? g_h1 : g_h2);
            int kk = k & 127;
            As[c][r] = (grow < N_NODES) ? base[grow * D + kk] : 0.0f;
        }
        // load B tile (BK x BN), fully coalesced
#pragma unroll
        for (int i = 0; i < 4; i++) {
            int idx = tid + i * 256;
            int r = idx >> 7;
            int c = idx & 127;
            Bs[r][c] = g_Wt[(k0 + r) * D + c];
        }
        __syncthreads();

#pragma unroll
        for (int kk = 0; kk < BK; kk++) {
            float ra[TM], rb[TN];
#pragma unroll
            for (int i = 0; i < TM; i++) ra[i] = As[kk][tr * TM + i];
#pragma unroll
            for (int j = 0; j < TN; j++) rb[j] = Bs[kk][tc * TN + j];
#pragma unroll
            for (int i = 0; i < TM; i++)
#pragma unroll
                for (int j = 0; j < TN; j++) acc[i][j] += ra[i] * rb[j];
        }
        __syncthreads();
    }

#pragma unroll
    for (int i = 0; i < TM; i++) {
        int grow = rowBase + tr * TM + i;
        if (grow < N_NODES) {
#pragma unroll
            for (int j = 0; j < TN; j++) {
                int col = tc * TN + j;
                out[grow * D + col] = acc[i][j] + bias[col];
            }
        }
    }
}

// ---------------------------------------------------------------------------
extern "C" void kernel_launch(void* const* d_in, const int* in_sizes, int n_in,
                              void* d_out, int out_size) {
    const float* feat = (const float*)d_in[0];
    const int*   src  = (const int*)d_in[1];   // int32 view; probe decides stride
    const int*   dst  = (const int*)d_in[2];
    const float* W    = (const float*)d_in[3];
    const float* bias = (const float*)d_in[4];
    float* out = (float*)d_out;

    const int E = in_sizes[1];

    float* norm; cudaGetSymbolAddress((void**)&norm, g_norm);
    float* h1;   cudaGetSymbolAddress((void**)&h1,   g_h1);
    float* h2;   cudaGetSymbolAddress((void**)&h2,   g_h2);

    // 0) index dtype probe
    detect_idx_kernel<<<1, 32>>>(dst);

    // 1) degree -> norm
    zero_kernel<<<(N_NODES + 255) / 256, 256>>>(norm, N_NODES);
    deg_kernel<<<(E + 255) / 256, 256>>>(dst, E);
    rsqrt_kernel<<<(N_NODES + 255) / 256, 256>>>();

    // 2) transpose W
    transpose_w_kernel<<<(D * FAN_IN + 255) / 256, 256>>>(W);

    // 3) hop 1: h1 = norm * A @ (feat * norm)
    zero_kernel<<<(N_NODES * D + 255) / 256, 256>>>(h1, N_NODES * D);
    scatter_kernel<<<(E + 1) / 2, 256>>>(feat, h1, src, dst, E);
    scale_kernel<<<(N_NODES * D + 255) / 256, 256>>>(h1);

    // 4) hop 2: h2 = norm * A @ (h1 * norm)
    zero_kernel<<<(N_NODES * D + 255) / 256, 256>>>(h2, N_NODES * D);
    scatter_kernel<<<(E + 1) / 2, 256>>>(h1, h2, src, dst, E);
    scale_kernel<<<(N_NODES * D + 255) / 256, 256>>>(h2);

    // 5) fused concat + linear
    gemm_kernel<<<(N_NODES + BM - 1) / BM, 256>>>(feat, bias, out);
}

// round 2
// speedup vs baseline: 2.3693x; 2.3693x over previous
#include <cuda_runtime.h>
#include <math.h>

#define N_NODES 100000
#define D 128
#define FAN_IN 384
#define E_MAX 1600000

// ---- scratch (__device__ globals; no allocations allowed) ----
__device__ __align__(16) float g_h1[N_NODES * D];
__device__ __align__(16) float g_h2[N_NODES * D];
__device__ float g_norm[N_NODES];
__device__ int   g_deg[N_NODES];
__device__ int   g_row[N_NODES + 1];
__device__ int   g_cursor[N_NODES];
__device__ int   g_csr[E_MAX];          // src index per edge, bucketed by dst
__device__ float g_Wt[FAN_IN * D];      // W transposed: Wt[k][o]
__device__ int   g_idx64;               // 1 if indices are int64, 0 if int32

// ---------------------------------------------------------------------------
// dtype probe: reference guarantees dst[0..N-1] == arange(N).
// int64 LE viewed as int32: [0,0,1,0,2,0,...]; int32: [0,1,2,...]
__global__ void detect_idx_kernel(const int* dst32) {
    if (threadIdx.x == 0 && blockIdx.x == 0)
        g_idx64 = (dst32[1] == 0 && dst32[2] == 1 && dst32[4] == 2) ? 1 : 0;
}

__device__ __forceinline__ int load_idx(const int* p, int e, int is64) {
    return is64 ? p[2 * e] : p[e];
}

// ---------------------------------------------------------------------------
__global__ void zero_deg_kernel() {
    int i = blockIdx.x * blockDim.x + threadIdx.x;
    if (i < N_NODES) g_deg[i] = 0;
}

__global__ void deg_kernel(const int* __restrict__ dst32, int E) {
    int e = blockIdx.x * blockDim.x + threadIdx.x;
    if (e < E) atomicAdd(&g_deg[load_idx(dst32, e, g_idx64)], 1);
}

// single-block 3-phase exclusive scan over g_deg -> g_row, g_cursor, g_norm
__global__ __launch_bounds__(1024)
void scan_kernel() {
    __shared__ int sums[1024];
    int tid = threadIdx.x;
    const int chunk = (N_NODES + 1023) / 1024;   // 98
    int begin = tid * chunk;
    int endi  = min(begin + chunk, N_NODES);
    int s = 0;
    for (int i = begin; i < endi; i++) s += g_deg[i];
    sums[tid] = s;
    __syncthreads();
    // Hillis-Steele inclusive scan
    for (int off = 1; off < 1024; off <<= 1) {
        int v = 0;
        if (tid >= off) v = sums[tid - off];
        __syncthreads();
        if (tid >= off) sums[tid] += v;
        __syncthreads();
    }
    int run = (tid == 0) ? 0 : sums[tid - 1];
    for (int i = begin; i < endi; i++) {
        g_row[i] = run;
        g_cursor[i] = run;
        int d = g_deg[i];
        g_norm[i] = rsqrtf((float)d);
        run += d;
    }
    if (endi == N_NODES && begin < N_NODES) g_row[N_NODES] = run;
    if (begin >= N_NODES && tid == 1023) g_row[N_NODES] = sums[1023];
}

__global__ void csr_fill_kernel(const int* __restrict__ src32,
                                const int* __restrict__ dst32, int E) {
    int e = blockIdx.x * blockDim.x + threadIdx.x;
    if (e >= E) return;
    int is64 = g_idx64;
    int t = load_idx(dst32, e, is64);
    int s = load_idx(src32, e, is64);
    int pos = atomicAdd(&g_cursor[t], 1);
    g_csr[pos] = s;
}

// W is [128][384] row-major; Wt[k][o] = W[o][k]
__global__ void transpose_w_kernel(const float* __restrict__ W) {
    int idx = blockIdx.x * blockDim.x + threadIdx.x;
    if (idx < D * FAN_IN) {
        int o = idx / FAN_IN;
        int k = idx % FAN_IN;
        g_Wt[k * D + o] = W[idx];
    }
}

// ---------------------------------------------------------------------------
// gather SpMM: hout[n] = norm[n] * sum_{e in CSR[n]} hin[csr[e]] * norm[csr[e]]
// one warp per node, float4 per lane (128 floats = 32 lanes x float4)
__global__ __launch_bounds__(256)
void gather_kernel(const float* __restrict__ hin, float* __restrict__ hout) {
    int warp = (blockIdx.x * 256 + threadIdx.x) >> 5;
    int lane = threadIdx.x & 31;
    if (warp >= N_NODES) return;
    int node  = warp;
    int start = g_row[node];
    int end   = g_row[node + 1];

    const float4* hin4 = (const float4*)hin;
    float ax = 0.f, ay = 0.f, az = 0.f, aw = 0.f;

    int e = start;
    for (; e + 2 <= end; e += 2) {
        int s0 = g_csr[e];
        int s1 = g_csr[e + 1];
        float n0 = g_norm[s0];
        float n1 = g_norm[s1];
        float4 v0 = __ldg(&hin4[s0 * 32 + lane]);
        float4 v1 = __ldg(&hin4[s1 * 32 + lane]);
        ax += v0.x * n0; ay += v0.y * n0; az += v0.z * n0; aw += v0.w * n0;
        ax += v1.x * n1; ay += v1.y * n1; az += v1.z * n1; aw += v1.w * n1;
    }
    if (e < end) {
        int s0 = g_csr[e];
        float n0 = g_norm[s0];
        float4 v0 = __ldg(&hin4[s0 * 32 + lane]);
        ax += v0.x * n0; ay += v0.y * n0; az += v0.z * n0; aw += v0.w * n0;
    }

    float nd = g_norm[node];
    float4 r = make_float4(ax * nd, ay * nd, az * nd, aw * nd);
    ((float4*)hout)[node * 32 + lane] = r;
}

// ---------------------------------------------------------------------------
// SGEMM: out[n][o] = b[o] + sum_k x[n][k] * Wt[k][o], x = [feat | h1 | h2]
#define BM 128
#define BN 128
#define BK 8
#define TM 8
#define TN 8

__global__ __launch_bounds__(256)
void gemm_kernel(const float* __restrict__ feat,
                 const float* __restrict__ bias,
                 float* __restrict__ out) {
    __shared__ float As[BK][BM];
    __shared__ float Bs[BK][BN];

    int rowBase = blockIdx.x * BM;
    int tid = threadIdx.x;
    int tr = tid / 16;
    int tc = tid % 16;

    float acc[TM][TN];
#pragma unroll
    for (int i = 0; i < TM; i++)
#pragma unroll
        for (int j = 0; j < TN; j++) acc[i][j] = 0.0f;

    for (int k0 = 0; k0 < FAN_IN; k0 += BK) {
        const float* base = (k0 < 128) ? feat : ((k0 < 256) ? g_h1 : g_h2);
        int kbase = k0 & 127;
#pragma unroll
        for (int i = 0; i < 4; i++) {
            int idx = tid + i * 256;
            int r = idx >> 3;
            int c = idx & 7;
            int grow = rowBase + r;
            As[c][r] = (grow < N_NODES) ? __ldg(&base[grow * D + kbase + c]) : 0.0f;
        }
#pragma unroll
        for (int i = 0; i < 4; i++) {
            int idx = tid + i * 256;
            int r = idx >> 7;
            int c = idx & 127;
            Bs[r][c] = g_Wt[(k0 + r) * D + c];
        }
        __syncthreads();

#pragma unroll
        for (int kk = 0; kk < BK; kk++) {
            float ra[TM], rb[TN];
#pragma unroll
            for (int i = 0; i < TM; i++) ra[i] = As[kk][tr * TM + i];
#pragma unroll
            for (int j = 0; j < TN; j++) rb[j] = Bs[kk][tc * TN + j];
#pragma unroll
            for (int i = 0; i < TM; i++)
#pragma unroll
                for (int j = 0; j < TN; j++) acc[i][j] += ra[i] * rb[j];
        }
        __syncthreads();
    }

#pragma unroll
    for (int i = 0; i < TM; i++) {
        int grow = rowBase + tr * TM + i;
        if (grow < N_NODES) {
#pragma unroll
            for (int j = 0; j < TN; j++) {
                int col = tc * TN + j;
                out[grow * D + col] = acc[i][j] + bias[col];
            }
        }
    }
}

// ---------------------------------------------------------------------------
extern "C" void kernel_launch(void* const* d_in, const int* in_sizes, int n_in,
                              void* d_out, int out_size) {
    const float* feat = (const float*)d_in[0];
    const int*   src  = (const int*)d_in[1];
    const int*   dst  = (const int*)d_in[2];
    const float* W    = (const float*)d_in[3];
    const float* bias = (const float*)d_in[4];
    float* out = (float*)d_out;

    const int E = in_sizes[1];

    float* h1; cudaGetSymbolAddress((void**)&h1, g_h1);
    float* h2; cudaGetSymbolAddress((void**)&h2, g_h2);

    detect_idx_kernel<<<1, 32>>>(dst);

    // CSR build
    zero_deg_kernel<<<(N_NODES + 255) / 256, 256>>>();
    deg_kernel<<<(E + 255) / 256, 256>>>(dst, E);
    scan_kernel<<<1, 1024>>>();
    csr_fill_kernel<<<(E + 255) / 256, 256>>>(src, dst, E);

    transpose_w_kernel<<<(D * FAN_IN + 255) / 256, 256>>>(W);

    // two SpMM hops, gather form (no atomics, no zero/scale passes)
    int gblocks = (N_NODES * 32 + 255) / 256;     // warp per node
    gather_kernel<<<gblocks, 256>>>(feat, h1);
    gather_kernel<<<gblocks, 256>>>(h1, h2);

    // fused concat + linear
    gemm_kernel<<<(N_NODES + BM - 1) / BM, 256>>>(feat, bias, out);
}

// round 3
// speedup vs baseline: 3.3732x; 1.4237x over previous
#include <cuda_runtime.h>
#include <math.h>

#define N_NODES 100000
#define D 128
#define FAN_IN 384
#define E_MAX 1600000
#define SCAN_BLOCKS ((N_NODES + 255) / 256)   // 391

// ---- scratch (__device__ globals; no allocations allowed) ----
__device__ __align__(16) float g_h1[N_NODES * D];
__device__ __align__(16) float g_h2[N_NODES * D];
__device__ float g_norm[N_NODES];
__device__ int   g_deg[N_NODES];
__device__ int   g_row[N_NODES + 1];
__device__ int   g_cursor[N_NODES];
__device__ int   g_csr[E_MAX];          // src index per edge, bucketed by dst
__device__ float g_Wt[FAN_IN * D];      // W transposed: Wt[k][o]
__device__ int   g_idx64;               // 1 if indices are int64, 0 if int32
__device__ int   g_bsum[SCAN_BLOCKS];
__device__ int   g_boff[SCAN_BLOCKS];

// ---------------------------------------------------------------------------
// dtype probe: reference guarantees dst[0..N-1] == arange(N).
__global__ void detect_idx_kernel(const int* dst32) {
    if (threadIdx.x == 0 && blockIdx.x == 0)
        g_idx64 = (dst32[1] == 0 && dst32[2] == 1 && dst32[4] == 2) ? 1 : 0;
}

__device__ __forceinline__ int load_idx(const int* p, int e, int is64) {
    return is64 ? p[2 * e] : p[e];
}

// ---------------------------------------------------------------------------
__global__ void zero_deg_kernel() {
    int i = blockIdx.x * blockDim.x + threadIdx.x;
    if (i < N_NODES) g_deg[i] = 0;
}

__global__ void deg_kernel(const int* __restrict__ dst32, int E) {
    int e = blockIdx.x * blockDim.x + threadIdx.x;
    if (e < E) atomicAdd(&g_deg[load_idx(dst32, e, g_idx64)], 1);
}

// --- parallel scan, 3 phases ---
__global__ __launch_bounds__(256)
void scan_phase1_kernel() {           // block sums of g_deg, 256/block
    __shared__ int wsum[8];
    int g = blockIdx.x * 256 + threadIdx.x;
    int v = (g < N_NODES) ? g_deg[g] : 0;
#pragma unroll
    for (int o = 16; o > 0; o >>= 1) v += __shfl_down_sync(0xffffffffu, v, o);
    if ((threadIdx.x & 31) == 0) wsum[threadIdx.x >> 5] = v;
    __syncthreads();
    if (threadIdx.x < 8) {
        int s = wsum[threadIdx.x];
#pragma unroll
        for (int o = 4; o > 0; o >>= 1) s += __shfl_down_sync(0xffu, s, o);
        if (threadIdx.x == 0) g_bsum[blockIdx.x] = s;
    }
}

__global__ __launch_bounds__(512)
void scan_phase2_kernel() {           // exclusive scan of 391 block sums
    __shared__ int sh[512];
    int t = threadIdx.x;
    sh[t] = (t < SCAN_BLOCKS) ? g_bsum[t] : 0;
    __syncthreads();
    for (int off = 1; off < 512; off <<= 1) {
        int v = (t >= off) ? sh[t - off] : 0;
        __syncthreads();
        sh[t] += v;
        __syncthreads();
    }
    if (t < SCAN_BLOCKS) g_boff[t] = (t == 0) ? 0 : sh[t - 1];
}

__global__ __launch_bounds__(256)
void scan_phase3_kernel() {           // per-block exclusive scan + offset
    __shared__ int wsum[8];
    int t = threadIdx.x;
    int g = blockIdx.x * 256 + t;
    int lane = t & 31, warp = t >> 5;
    int v = (g < N_NODES) ? g_deg[g] : 0;
    // warp inclusive scan
    int inc = v;
#pragma unroll
    for (int o = 1; o < 32; o <<= 1) {
        int u = __shfl_up_sync(0xffffffffu, inc, o);
        if (lane >= o) inc += u;
    }
    if (lane == 31) wsum[warp] = inc;
    __syncthreads();
    if (t < 8) {
        int s = wsum[t];
        int si = s;
#pragma unroll
        for (int o = 1; o < 8; o <<= 1) {
            int u = __shfl_up_sync(0xffu, si, o);
            if (t >= o) si += u;
        }
        wsum[t] = si - s;   // exclusive warp offset
    }
    __syncthreads();
    if (g < N_NODES) {
        int row = g_boff[blockIdx.x] + wsum[warp] + inc - v;  // exclusive
        g_row[g] = row;
        g_cursor[g] = row;
        g_norm[g] = rsqrtf((float)v);
        if (g == N_NODES - 1) g_row[N_NODES] = row + v;
    }
}

__global__ void csr_fill_kernel(const int* __restrict__ src32,
                                const int* __restrict__ dst32, int E) {
    int e = blockIdx.x * blockDim.x + threadIdx.x;
    if (e >= E) return;
    int is64 = g_idx64;
    int t = load_idx(dst32, e, is64);
    int s = load_idx(src32, e, is64);
    int pos = atomicAdd(&g_cursor[t], 1);
    g_csr[pos] = s;
}

// W is [128][384] row-major; Wt[k][o] = W[o][k]
__global__ void transpose_w_kernel(const float* __restrict__ W) {
    int idx = blockIdx.x * blockDim.x + threadIdx.x;
    if (idx < D * FAN_IN) {
        int o = idx / FAN_IN;
        int k = idx % FAN_IN;
        g_Wt[k * D + o] = W[idx];
    }
}

// ---------------------------------------------------------------------------
// gather SpMM: hout[n] = norm[n] * sum_{e in CSR[n]} hin[csr[e]] * norm[csr[e]]
// one warp per node, float4 per lane
__global__ __launch_bounds__(256)
void gather_kernel(const float* __restrict__ hin, float* __restrict__ hout) {
    int warp = (blockIdx.x * 256 + threadIdx.x) >> 5;
    int lane = threadIdx.x & 31;
    if (warp >= N_NODES) return;
    int node  = warp;
    int start = g_row[node];
    int end   = g_row[node + 1];

    const float4* hin4 = (const float4*)hin;
    float ax = 0.f, ay = 0.f, az = 0.f, aw = 0.f;

    int e = start;
    for (; e + 4 <= end; e += 4) {
        int s0 = g_csr[e],     s1 = g_csr[e + 1];
        int s2 = g_csr[e + 2], s3 = g_csr[e + 3];
        float n0 = g_norm[s0], n1 = g_norm[s1];
        float n2 = g_norm[s2], n3 = g_norm[s3];
        float4 v0 = __ldg(&hin4[s0 * 32 + lane]);
        float4 v1 = __ldg(&hin4[s1 * 32 + lane]);
        float4 v2 = __ldg(&hin4[s2 * 32 + lane]);
        float4 v3 = __ldg(&hin4[s3 * 32 + lane]);
        ax += v0.x * n0; ay += v0.y * n0; az += v0.z * n0; aw += v0.w * n0;
        ax += v1.x * n1; ay += v1.y * n1; az += v1.z * n1; aw += v1.w * n1;
        ax += v2.x * n2; ay += v2.y * n2; az += v2.z * n2; aw += v2.w * n2;
        ax += v3.x * n3; ay += v3.y * n3; az += v3.z * n3; aw += v3.w * n3;
    }
    for (; e < end; e++) {
        int s0 = g_csr[e];
        float n0 = g_norm[s0];
        float4 v0 = __ldg(&hin4[s0 * 32 + lane]);
        ax += v0.x * n0; ay += v0.y * n0; az += v0.z * n0; aw += v0.w * n0;
    }

    float nd = g_norm[node];
    ((float4*)hout)[node * 32 + lane] =
        make_float4(ax * nd, ay * nd, az * nd, aw * nd);
}

// ---------------------------------------------------------------------------
// SGEMM: out[n][o] = b[o] + sum_k x[n][k] * Wt[k][o], x = [feat | h1 | h2]
#define BM 128
#define BN 128
#define BK 8
#define TM 8
#define TN 8

__global__ __launch_bounds__(256)
void gemm_kernel(const float* __restrict__ feat,
                 const float* __restrict__ bias,
                 float* __restrict__ out) {
    __shared__ float As[BK][BM];
    __shared__ float Bs[BK][BN];

    int rowBase = blockIdx.x * BM;
    int tid = threadIdx.x;
    int tr = tid / 16;
    int tc = tid % 16;

    float acc[TM][TN];
#pragma unroll
    for (int i = 0; i < TM; i++)
#pragma unroll
        for (int j = 0; j < TN; j++) acc[i][j] = 0.0f;

    for (int k0 = 0; k0 < FAN_IN; k0 += BK) {
        const float* base = (k0 < 128) ? feat : ((k0 < 256) ? g_h1 : g_h2);
        int kbase = k0 & 127;
#pragma unroll
        for (int i = 0; i < 4; i++) {
            int idx = tid + i * 256;
            int r = idx >> 3;
            int c = idx & 7;
            int grow = rowBase + r;
            As[c][r] = (grow < N_NODES) ? __ldg(&base[grow * D + kbase + c]) : 0.0f;
        }
#pragma unroll
        for (int i = 0; i < 4; i++) {
            int idx = tid + i * 256;
            int r = idx >> 7;
            int c = idx & 127;
            Bs[r][c] = g_Wt[(k0 + r) * D + c];
        }
        __syncthreads();

#pragma unroll
        for (int kk = 0; kk < BK; kk++) {
            float ra[TM], rb[TN];
#pragma unroll
            for (int i = 0; i < TM; i++) ra[i] = As[kk][tr * TM + i];
#pragma unroll
            for (int j = 0; j < TN; j++) rb[j] = Bs[kk][tc * TN + j];
#pragma unroll
            for (int i = 0; i < TM; i++)
#pragma unroll
                for (int j = 0; j < TN; j++) acc[i][j] += ra[i] * rb[j];
        }
        __syncthreads();
    }

#pragma unroll
    for (int i = 0; i < TM; i++) {
        int grow = rowBase + tr * TM + i;
        if (grow < N_NODES) {
#pragma unroll
            for (int j = 0; j < TN; j++) {
                int col = tc * TN + j;
                out[grow * D + col] = acc[i][j] + bias[col];
            }
        }
    }
}

// ---------------------------------------------------------------------------
extern "C" void kernel_launch(void* const* d_in, const int* in_sizes, int n_in,
                              void* d_out, int out_size) {
    const float* feat = (const float*)d_in[0];
    const int*   src  = (const int*)d_in[1];
    const int*   dst  = (const int*)d_in[2];
    const float* W    = (const float*)d_in[3];
    const float* bias = (const float*)d_in[4];
    float* out = (float*)d_out;

    const int E = in_sizes[1];

    float* h1; cudaGetSymbolAddress((void**)&h1, g_h1);
    float* h2; cudaGetSymbolAddress((void**)&h2, g_h2);

    detect_idx_kernel<<<1, 32>>>(dst);

    // CSR build
    zero_deg_kernel<<<(N_NODES + 255) / 256, 256>>>();
    deg_kernel<<<(E + 255) / 256, 256>>>(dst, E);
    scan_phase1_kernel<<<SCAN_BLOCKS, 256>>>();
    scan_phase2_kernel<<<1, 512>>>();
    scan_phase3_kernel<<<SCAN_BLOCKS, 256>>>();
    csr_fill_kernel<<<(E + 255) / 256, 256>>>(src, dst, E);

    transpose_w_kernel<<<(D * FAN_IN + 255) / 256, 256>>>(W);

    // two SpMM hops, gather form
    int gblocks = (N_NODES * 32 + 255) / 256;
    gather_kernel<<<gblocks, 256>>>(feat, h1);
    gather_kernel<<<gblocks, 256>>>(h1, h2);

    // fused concat + linear
    gemm_kernel<<<(N_NODES + BM - 1) / BM, 256>>>(feat, bias, out);
}

// round 5
// speedup vs baseline: 7.0076x; 2.0775x over previous
#include <cuda_runtime.h>
#include <cuda_fp16.h>
#include <math.h>
#include <stdint.h>

#define N_NODES 100000
#define D 128
#define FAN_IN 384
#define E_MAX 1600000
#define SCAN_BLOCKS ((N_NODES + 255) / 256)   // 391

// ---- scratch (__device__ globals; no allocations allowed) ----
__device__ __align__(16) float g_h1[N_NODES * D];
__device__ __align__(16) float g_h2[N_NODES * D];
__device__ float g_norm[N_NODES];
__device__ int   g_deg[N_NODES];
__device__ int   g_row[N_NODES + 1];
__device__ int   g_cursor[N_NODES];
__device__ int   g_csr[E_MAX];
__device__ int   g_idx64;
__device__ int   g_bsum[SCAN_BLOCKS];
__device__ int   g_boff[SCAN_BLOCKS];

// ---------------------------------------------------------------------------
__global__ void detect_idx_kernel(const int* dst32) {
    if (threadIdx.x == 0 && blockIdx.x == 0)
        g_idx64 = (dst32[1] == 0 && dst32[2] == 1 && dst32[4] == 2) ? 1 : 0;
}

__device__ __forceinline__ int load_idx(const int* p, int e, int is64) {
    return is64 ? p[2 * e] : p[e];
}

// ---------------------------------------------------------------------------
__global__ void zero_deg_kernel() {
    int i = blockIdx.x * blockDim.x + threadIdx.x;
    if (i < N_NODES) g_deg[i] = 0;
}

__global__ void deg_kernel(const int* __restrict__ dst32, int E) {
    int e = blockIdx.x * blockDim.x + threadIdx.x;
    if (e < E) atomicAdd(&g_deg[load_idx(dst32, e, g_idx64)], 1);
}

__global__ __launch_bounds__(256)
void scan_phase1_kernel() {
    __shared__ int wsum[8];
    int g = blockIdx.x * 256 + threadIdx.x;
    int v = (g < N_NODES) ? g_deg[g] : 0;
#pragma unroll
    for (int o = 16; o > 0; o >>= 1) v += __shfl_down_sync(0xffffffffu, v, o);
    if ((threadIdx.x & 31) == 0) wsum[threadIdx.x >> 5] = v;
    __syncthreads();
    if (threadIdx.x < 8) {
        int s = wsum[threadIdx.x];
#pragma unroll
        for (int o = 4; o > 0; o >>= 1) s += __shfl_down_sync(0xffu, s, o);
        if (threadIdx.x == 0) g_bsum[blockIdx.x] = s;
    }
}

__global__ __launch_bounds__(512)
void scan_phase2_kernel() {
    __shared__ int sh[512];
    int t = threadIdx.x;
    sh[t] = (t < SCAN_BLOCKS) ? g_bsum[t] : 0;
    __syncthreads();
    for (int off = 1; off < 512; off <<= 1) {
        int v = (t >= off) ? sh[t - off] : 0;
        __syncthreads();
        sh[t] += v;
        __syncthreads();
    }
    if (t < SCAN_BLOCKS) g_boff[t] = (t == 0) ? 0 : sh[t - 1];
}

__global__ __launch_bounds__(256)
void scan_phase3_kernel() {
    __shared__ int wsum[8];
    int t = threadIdx.x;
    int g = blockIdx.x * 256 + t;
    int lane = t & 31, warp = t >> 5;
    int v = (g < N_NODES) ? g_deg[g] : 0;
    int inc = v;
#pragma unroll
    for (int o = 1; o < 32; o <<= 1) {
        int u = __shfl_up_sync(0xffffffffu, inc, o);
        if (lane >= o) inc += u;
    }
    if (lane == 31) wsum[warp] = inc;
    __syncthreads();
    if (t < 8) {
        int s = wsum[t];
        int si = s;
#pragma unroll
        for (int o = 1; o < 8; o <<= 1) {
            int u = __shfl_up_sync(0xffu, si, o);
            if (t >= o) si += u;
        }
        wsum[t] = si - s;
    }
    __syncthreads();
    if (g < N_NODES) {
        int row = g_boff[blockIdx.x] + wsum[warp] + inc - v;
        g_row[g] = row;
        g_cursor[g] = row;
        g_norm[g] = rsqrtf((float)v);
        if (g == N_NODES - 1) g_row[N_NODES] = row + v;
    }
}

__global__ void csr_fill_kernel(const int* __restrict__ src32,
                                const int* __restrict__ dst32, int E) {
    int e = blockIdx.x * blockDim.x + threadIdx.x;
    if (e >= E) return;
    int is64 = g_idx64;
    int t = load_idx(dst32, e, is64);
    int s = load_idx(src32, e, is64);
    int pos = atomicAdd(&g_cursor[t], 1);
    g_csr[pos] = s;
}

// ---------------------------------------------------------------------------
// gather SpMM: hout[n] = norm[n] * sum_{e} hin[csr[e]] * norm[csr[e]]
__global__ __launch_bounds__(256)
void gather_kernel(const float* __restrict__ hin, float* __restrict__ hout) {
    int warp = (blockIdx.x * 256 + threadIdx.x) >> 5;
    int lane = threadIdx.x & 31;
    if (warp >= N_NODES) return;
    int node  = warp;
    int start = g_row[node];
    int end   = g_row[node + 1];

    const float4* hin4 = (const float4*)hin;
    float ax = 0.f, ay = 0.f, az = 0.f, aw = 0.f;

    int e = start;
    for (; e + 4 <= end; e += 4) {
        int s0 = g_csr[e],     s1 = g_csr[e + 1];
        int s2 = g_csr[e + 2], s3 = g_csr[e + 3];
        float n0 = g_norm[s0], n1 = g_norm[s1];
        float n2 = g_norm[s2], n3 = g_norm[s3];
        float4 v0 = __ldg(&hin4[s0 * 32 + lane]);
        float4 v1 = __ldg(&hin4[s1 * 32 + lane]);
        float4 v2 = __ldg(&hin4[s2 * 32 + lane]);
        float4 v3 = __ldg(&hin4[s3 * 32 + lane]);
        ax += v0.x * n0; ay += v0.y * n0; az += v0.z * n0; aw += v0.w * n0;
        ax += v1.x * n1; ay += v1.y * n1; az += v1.z * n1; aw += v1.w * n1;
        ax += v2.x * n2; ay += v2.y * n2; az += v2.z * n2; aw += v2.w * n2;
        ax += v3.x * n3; ay += v3.y * n3; az += v3.z * n3; aw += v3.w * n3;
    }
    for (; e < end; e++) {
        int s0 = g_csr[e];
        float n0 = g_norm[s0];
        float4 v0 = __ldg(&hin4[s0 * 32 + lane]);
        ax += v0.x * n0; ay += v0.y * n0; az += v0.z * n0; aw += v0.w * n0;
    }

    float nd = g_norm[node];
    ((float4*)hout)[node * 32 + lane] =
        make_float4(ax * nd, ay * nd, az * nd, aw * nd);
}

// ---------------------------------------------------------------------------
// HMMA fp16 GEMM: out[n][o] = bias[o] + sum_k x[n][k] * W[o][k]
// x = [feat | h1 | h2]. mma.sync.m16n8k16.row.col, A=x (row-major),
// B=W (n-major contiguous-in-k == "col"). K processed in 6 chunks of 64.
// Per CTA: 128x128 tile. 8 warps in 2x4: each 64 rows x 32 cols.

__device__ __forceinline__ uint32_t smem_u32(const void* p) {
    uint32_t a;
    asm("{ .reg .u64 t; cvta.to.shared.u64 t, %1; cvt.u32.u64 %0, t; }"
        : "=r"(a) : "l"(p));
    return a;
}
// rows are 128B; swizzle 16B columns by low 3 row bits
__device__ __forceinline__ uint32_t sw128(uint32_t off) {
    return off ^ ((off >> 3) & 0x70);
}

__global__ __launch_bounds__(256)
void gemm_hmma_kernel(const float* __restrict__ feat,
                      const float* __restrict__ W,
                      const float* __restrict__ bias,
                      float* __restrict__ out) {
    __shared__ __align__(128) char smA[128 * 128];   // 128 rows x 64 halves
    __shared__ __align__(128) char smB[128 * 128];   // 128 n    x 64 halves

    int tid = threadIdx.x;
    int wid = tid >> 5;
    int lane = tid & 31;
    int warp_m = wid >> 2;          // 0..1  -> 64-row slab
    int warp_n = wid & 3;           // 0..3  -> 32-col slab
    int rowBase = blockIdx.x * 128;

    uint32_t sa = smem_u32(smA);
    uint32_t sb = smem_u32(smB);

    float acc[4][4][4];
#pragma unroll
    for (int i = 0; i < 4; i++)
#pragma unroll
        for (int j = 0; j < 4; j++)
#pragma unroll
            for (int q = 0; q < 4; q++) acc[i][j][q] = 0.f;

    for (int ch = 0; ch < 6; ch++) {
        const float* base = (ch < 2) ? feat : ((ch < 4) ? g_h1 : g_h2);
        int koff = (ch & 1) * 64;
        // load A chunk: 128 rows x 32 float2 -> half2, swizzled
#pragma unroll
        for (int it = 0; it < 16; it++) {
            int idx = tid + it * 256;
            int r = idx >> 5;
            int j = idx & 31;
            int grow = rowBase + r;
            float2 v = make_float2(0.f, 0.f);
            if (grow < N_NODES) v = *(const float2*)&base[grow * D + koff + j * 2];
            __half2 h = __floats2half2_rn(v.x, v.y);
            *(uint32_t*)(smA + sw128((uint32_t)(r * 128 + j * 4))) = *(uint32_t*)&h;
        }
        // load B chunk: W[o][ch*64 + j*2]
#pragma unroll
        for (int it = 0; it < 16; it++) {
            int idx = tid + it * 256;
            int r = idx >> 5;
            int j = idx & 31;
            float2 v = *(const float2*)&W[r * FAN_IN + ch * 64 + j * 2];
            __half2 h = __floats2half2_rn(v.x, v.y);
            *(uint32_t*)(smB + sw128((uint32_t)(r * 128 + j * 4))) = *(uint32_t*)&h;
        }
        __syncthreads();

#pragma unroll
        for (int kk = 0; kk < 4; kk++) {       // k16 steps within chunk
            uint32_t afrag[4][4];
#pragma unroll
            for (int mi = 0; mi < 4; mi++) {
                int r = warp_m * 64 + mi * 16 + (lane & 15);
                uint32_t addr = sa + sw128((uint32_t)(r * 128 + kk * 32 + (lane >> 4) * 16));
                asm volatile(
                    "ldmatrix.sync.aligned.m8n8.x4.shared.b16 {%0,%1,%2,%3}, [%4];"
                    : "=r"(afrag[mi][0]), "=r"(afrag[mi][1]),
                      "=r"(afrag[mi][2]), "=r"(afrag[mi][3])
                    : "r"(addr));
            }
            uint32_t bfrag[4][2];
#pragma unroll
            for (int ni = 0; ni < 4; ni++) {
                int nr = warp_n * 32 + ni * 8 + (lane & 7);
                uint32_t addr = sb + sw128((uint32_t)(nr * 128 + kk * 32 + ((lane >> 3) & 1) * 16));
                asm volatile(
                    "ldmatrix.sync.aligned.m8n8.x2.shared.b16 {%0,%1}, [%2];"
                    : "=r"(bfrag[ni][0]), "=r"(bfrag[ni][1])
                    : "r"(addr));
            }
#pragma unroll
            for (int mi = 0; mi < 4; mi++)
#pragma unroll
                for (int ni = 0; ni < 4; ni++) {
                    asm volatile(
                        "mma.sync.aligned.m16n8k16.row.col.f32.f16.f16.f32 "
                        "{%0,%1,%2,%3}, {%4,%5,%6,%7}, {%8,%9}, {%0,%1,%2,%3};"
                        : "+f"(acc[mi][ni][0]), "+f"(acc[mi][ni][1]),
                          "+f"(acc[mi][ni][2]), "+f"(acc[mi][ni][3])
                        : "r"(afrag[mi][0]), "r"(afrag[mi][1]),
                          "r"(afrag[mi][2]), "r"(afrag[mi][3]),
                          "r"(bfrag[ni][0]), "r"(bfrag[ni][1]));
                }
        }
        __syncthreads();
    }

    // epilogue: c0,c1 -> (row = lane/4, col = (lane%4)*2), c2,c3 -> row+8
#pragma unroll
    for (int mi = 0; mi < 4; mi++) {
        int r0 = rowBase + warp_m * 64 + mi * 16 + (lane >> 2);
#pragma unroll
        for (int ni = 0; ni < 4; ni++) {
            int col = warp_n * 32 + ni * 8 + (lane & 3) * 2;
            float b0 = __ldg(&bias[col]);
            float b1 = __ldg(&bias[col + 1]);
            if (r0 < N_NODES) {
                float2 o0 = make_float2(acc[mi][ni][0] + b0, acc[mi][ni][1] + b1);
                *(float2*)&out[r0 * D + col] = o0;
            }
            if (r0 + 8 < N_NODES) {
                float2 o1 = make_float2(acc[mi][ni][2] + b0, acc[mi][ni][3] + b1);
                *(float2*)&out[(r0 + 8) * D + col] = o1;
            }
        }
    }
}

// ---------------------------------------------------------------------------
extern "C" void kernel_launch(void* const* d_in, const int* in_sizes, int n_in,
                              void* d_out, int out_size) {
    const float* feat = (const float*)d_in[0];
    const int*   src  = (const int*)d_in[1];
    const int*   dst  = (const int*)d_in[2];
    const float* W    = (const float*)d_in[3];
    const float* bias = (const float*)d_in[4];
    float* out = (float*)d_out;

    const int E = in_sizes[1];

    float* h1; cudaGetSymbolAddress((void**)&h1, g_h1);
    float* h2; cudaGetSymbolAddress((void**)&h2, g_h2);

    detect_idx_kernel<<<1, 32>>>(dst);

    // CSR build
    zero_deg_kernel<<<(N_NODES + 255) / 256, 256>>>();
    deg_kernel<<<(E + 255) / 256, 256>>>(dst, E);
    scan_phase1_kernel<<<SCAN_BLOCKS, 256>>>();
    scan_phase2_kernel<<<1, 512>>>();
    scan_phase3_kernel<<<SCAN_BLOCKS, 256>>>();
    csr_fill_kernel<<<(E + 255) / 256, 256>>>(src, dst, E);

    // two SpMM hops
    int gblocks = (N_NODES * 32 + 255) / 256;
    gather_kernel<<<gblocks, 256>>>(feat, h1);
    gather_kernel<<<gblocks, 256>>>(h1, h2);

    // fused concat + linear on tensor cores (HMMA mma.sync)
    int gemmBlocks = (N_NODES + 127) / 128;   // 782
    gemm_hmma_kernel<<<gemmBlocks, 256>>>(feat, W, bias, out);
}

// round 6
// speedup vs baseline: 7.2503x; 1.0346x over previous
#include <cuda_runtime.h>
#include <cuda_fp16.h>
#include <math.h>
#include <stdint.h>

#define N_NODES 100000
#define D 128
#define FAN_IN 384
#define E_MAX 1600000
#define SCAN_BLOCKS ((N_NODES + 255) / 256)   // 391

// ---- scratch (__device__ globals; no allocations allowed) ----
__device__ __align__(16) __half g_featH[N_NODES * D];
__device__ __align__(16) __half g_h1H[N_NODES * D];
__device__ __align__(16) __half g_h2H[N_NODES * D];
__device__ float g_norm[N_NODES];
__device__ int   g_deg[N_NODES];
__device__ int   g_row[N_NODES + 1];
__device__ int   g_cursor[N_NODES];
__device__ int   g_csr[E_MAX];
__device__ int   g_idx64;
__device__ int   g_bsum[SCAN_BLOCKS];
__device__ int   g_boff[SCAN_BLOCKS];

// ---------------------------------------------------------------------------
__global__ void detect_idx_kernel(const int* dst32) {
    if (threadIdx.x == 0 && blockIdx.x == 0)
        g_idx64 = (dst32[1] == 0 && dst32[2] == 1 && dst32[4] == 2) ? 1 : 0;
}

__device__ __forceinline__ int load_idx(const int* p, int e, int is64) {
    return is64 ? p[2 * e] : p[e];
}

// ---------------------------------------------------------------------------
__global__ void zero_deg_kernel() {
    int i = blockIdx.x * blockDim.x + threadIdx.x;
    if (i < N_NODES) g_deg[i] = 0;
}

__global__ void deg_kernel(const int* __restrict__ dst32, int E) {
    int e = blockIdx.x * blockDim.x + threadIdx.x;
    if (e < E) atomicAdd(&g_deg[load_idx(dst32, e, g_idx64)], 1);
}

__global__ __launch_bounds__(256)
void scan_phase1_kernel() {
    __shared__ int wsum[8];
    int g = blockIdx.x * 256 + threadIdx.x;
    int v = (g < N_NODES) ? g_deg[g] : 0;
#pragma unroll
    for (int o = 16; o > 0; o >>= 1) v += __shfl_down_sync(0xffffffffu, v, o);
    if ((threadIdx.x & 31) == 0) wsum[threadIdx.x >> 5] = v;
    __syncthreads();
    if (threadIdx.x < 8) {
        int s = wsum[threadIdx.x];
#pragma unroll
        for (int o = 4; o > 0; o >>= 1) s += __shfl_down_sync(0xffu, s, o);
        if (threadIdx.x == 0) g_bsum[blockIdx.x] = s;
    }
}

__global__ __launch_bounds__(512)
void scan_phase2_kernel() {
    __shared__ int sh[512];
    int t = threadIdx.x;
    sh[t] = (t < SCAN_BLOCKS) ? g_bsum[t] : 0;
    __syncthreads();
    for (int off = 1; off < 512; off <<= 1) {
        int v = (t >= off) ? sh[t - off] : 0;
        __syncthreads();
        sh[t] += v;
        __syncthreads();
    }
    if (t < SCAN_BLOCKS) g_boff[t] = (t == 0) ? 0 : sh[t - 1];
}

__global__ __launch_bounds__(256)
void scan_phase3_kernel() {
    __shared__ int wsum[8];
    int t = threadIdx.x;
    int g = blockIdx.x * 256 + t;
    int lane = t & 31, warp = t >> 5;
    int v = (g < N_NODES) ? g_deg[g] : 0;
    int inc = v;
#pragma unroll
    for (int o = 1; o < 32; o <<= 1) {
        int u = __shfl_up_sync(0xffffffffu, inc, o);
        if (lane >= o) inc += u;
    }
    if (lane == 31) wsum[warp] = inc;
    __syncthreads();
    if (t < 8) {
        int s = wsum[t];
        int si = s;
#pragma unroll
        for (int o = 1; o < 8; o <<= 1) {
            int u = __shfl_up_sync(0xffu, si, o);
            if (t >= o) si += u;
        }
        wsum[t] = si - s;
    }
    __syncthreads();
    if (g < N_NODES) {
        int row = g_boff[blockIdx.x] + wsum[warp] + inc - v;
        g_row[g] = row;
        g_cursor[g] = row;
        g_norm[g] = rsqrtf((float)v);
        if (g == N_NODES - 1) g_row[N_NODES] = row + v;
    }
}

__global__ void csr_fill_kernel(const int* __restrict__ src32,
                                const int* __restrict__ dst32, int E) {
    int e = blockIdx.x * blockDim.x + threadIdx.x;
    if (e >= E) return;
    int is64 = g_idx64;
    int t = load_idx(dst32, e, is64);
    int s = load_idx(src32, e, is64);
    int pos = atomicAdd(&g_cursor[t], 1);
    g_csr[pos] = s;
}

// ---------------------------------------------------------------------------
// feat fp32 -> fp16
__global__ void convert_feat_kernel(const float* __restrict__ feat) {
    int i = blockIdx.x * blockDim.x + threadIdx.x;   // over N*D/2
    if (i < N_NODES * D / 2) {
        float2 v = *(const float2*)&feat[i * 2];
        ((__half2*)g_featH)[i] = __floats2half2_rn(v.x, v.y);
    }
}

// ---------------------------------------------------------------------------
// gather SpMM (fp16 I/O, fp32 accumulate):
// hout[n] = half( norm[n] * sum_e hin[csr[e]] * norm[csr[e]] )
// one warp per node; each lane owns 4 halves (8 bytes)
__global__ __launch_bounds__(256)
void gather_kernel(const __half* __restrict__ hin, __half* __restrict__ hout) {
    int warp = (blockIdx.x * 256 + threadIdx.x) >> 5;
    int lane = threadIdx.x & 31;
    if (warp >= N_NODES) return;
    int node  = warp;
    int start = g_row[node];
    int end   = g_row[node + 1];

    const uint2* hin2 = (const uint2*)hin;   // 4 halves per uint2
    float ax = 0.f, ay = 0.f, az = 0.f, aw = 0.f;

    int e = start;
    for (; e + 4 <= end; e += 4) {
        int s0 = g_csr[e],     s1 = g_csr[e + 1];
        int s2 = g_csr[e + 2], s3 = g_csr[e + 3];
        float n0 = g_norm[s0], n1 = g_norm[s1];
        float n2 = g_norm[s2], n3 = g_norm[s3];
        uint2 r0 = __ldg(&hin2[s0 * 32 + lane]);
        uint2 r1 = __ldg(&hin2[s1 * 32 + lane]);
        uint2 r2 = __ldg(&hin2[s2 * 32 + lane]);
        uint2 r3 = __ldg(&hin2[s3 * 32 + lane]);
        float2 a0 = __half22float2(*(__half2*)&r0.x), b0 = __half22float2(*(__half2*)&r0.y);
        float2 a1 = __half22float2(*(__half2*)&r1.x), b1 = __half22float2(*(__half2*)&r1.y);
        float2 a2 = __half22float2(*(__half2*)&r2.x), b2 = __half22float2(*(__half2*)&r2.y);
        float2 a3 = __half22float2(*(__half2*)&r3.x), b3 = __half22float2(*(__half2*)&r3.y);
        ax += a0.x * n0; ay += a0.y * n0; az += b0.x * n0; aw += b0.y * n0;
        ax += a1.x * n1; ay += a1.y * n1; az += b1.x * n1; aw += b1.y * n1;
        ax += a2.x * n2; ay += a2.y * n2; az += b2.x * n2; aw += b2.y * n2;
        ax += a3.x * n3; ay += a3.y * n3; az += b3.x * n3; aw += b3.y * n3;
    }
    for (; e < end; e++) {
        int s0 = g_csr[e];
        float n0 = g_norm[s0];
        uint2 r0 = __ldg(&hin2[s0 * 32 + lane]);
        float2 a0 = __half22float2(*(__half2*)&r0.x), b0 = __half22float2(*(__half2*)&r0.y);
        ax += a0.x * n0; ay += a0.y * n0; az += b0.x * n0; aw += b0.y * n0;
    }

    float nd = g_norm[node];
    __half2 lo = __floats2half2_rn(ax * nd, ay * nd);
    __half2 hi = __floats2half2_rn(az * nd, aw * nd);
    uint2 o;
    o.x = *(uint32_t*)&lo;
    o.y = *(uint32_t*)&hi;
    ((uint2*)hout)[node * 32 + lane] = o;
}

// ---------------------------------------------------------------------------
// HMMA fp16 GEMM: out[n][o] = bias[o] + sum_k x[n][k] * W[o][k]
// x = [featH | h1H | h2H] (already fp16). Per CTA: 128x128 tile, 8 warps 2x4.

__device__ __forceinline__ uint32_t smem_u32(const void* p) {
    uint32_t a;
    asm("{ .reg .u64 t; cvta.to.shared.u64 t, %1; cvt.u32.u64 %0, t; }"
        : "=r"(a) : "l"(p));
    return a;
}
__device__ __forceinline__ uint32_t sw128(uint32_t off) {
    return off ^ ((off >> 3) & 0x70);
}

__global__ __launch_bounds__(256)
void gemm_hmma_kernel(const float* __restrict__ W,
                      const float* __restrict__ bias,
                      float* __restrict__ out) {
    __shared__ __align__(128) char smA[128 * 128];
    __shared__ __align__(128) char smB[128 * 128];

    int tid = threadIdx.x;
    int wid = tid >> 5;
    int lane = tid & 31;
    int warp_m = wid >> 2;
    int warp_n = wid & 3;
    int rowBase = blockIdx.x * 128;

    uint32_t sa = smem_u32(smA);
    uint32_t sb = smem_u32(smB);

    float acc[4][4][4];
#pragma unroll
    for (int i = 0; i < 4; i++)
#pragma unroll
        for (int j = 0; j < 4; j++)
#pragma unroll
            for (int q = 0; q < 4; q++) acc[i][j][q] = 0.f;

    for (int ch = 0; ch < 6; ch++) {
        const __half* baseH = (ch < 2) ? g_featH : ((ch < 4) ? g_h1H : g_h2H);
        int koff = (ch & 1) * 64;
        // A chunk: 128 rows x 64 halves; 16B (8 halves) per thread-iter
#pragma unroll
        for (int it = 0; it < 4; it++) {
            int idx = tid + it * 256;
            int r = idx >> 3;
            int j = idx & 7;
            int grow = rowBase + r;
            uint4 v = make_uint4(0, 0, 0, 0);
            if (grow < N_NODES)
                v = *(const uint4*)&baseH[grow * D + koff + j * 8];
            *(uint4*)(smA + sw128((uint32_t)(r * 128 + j * 16))) = v;
        }
        // B chunk: convert W fp32->fp16
#pragma unroll
        for (int it = 0; it < 16; it++) {
            int idx = tid + it * 256;
            int r = idx >> 5;
            int j = idx & 31;
            float2 v = *(const float2*)&W[r * FAN_IN + ch * 64 + j * 2];
            __half2 h = __floats2half2_rn(v.x, v.y);
            *(uint32_t*)(smB + sw128((uint32_t)(r * 128 + j * 4))) = *(uint32_t*)&h;
        }
        __syncthreads();

#pragma unroll
        for (int kk = 0; kk < 4; kk++) {
            uint32_t afrag[4][4];
#pragma unroll
            for (int mi = 0; mi < 4; mi++) {
                int r = warp_m * 64 + mi * 16 + (lane & 15);
                uint32_t addr = sa + sw128((uint32_t)(r * 128 + kk * 32 + (lane >> 4) * 16));
                asm volatile(
                    "ldmatrix.sync.aligned.m8n8.x4.shared.b16 {%0,%1,%2,%3}, [%4];"
                    : "=r"(afrag[mi][0]), "=r"(afrag[mi][1]),
                      "=r"(afrag[mi][2]), "=r"(afrag[mi][3])
                    : "r"(addr));
            }
            uint32_t bfrag[4][2];
#pragma unroll
            for (int ni = 0; ni < 4; ni++) {
                int nr = warp_n * 32 + ni * 8 + (lane & 7);
                uint32_t addr = sb + sw128((uint32_t)(nr * 128 + kk * 32 + ((lane >> 3) & 1) * 16));
                asm volatile(
                    "ldmatrix.sync.aligned.m8n8.x2.shared.b16 {%0,%1}, [%2];"
                    : "=r"(bfrag[ni][0]), "=r"(bfrag[ni][1])
                    : "r"(addr));
            }
#pragma unroll
            for (int mi = 0; mi < 4; mi++)
#pragma unroll
                for (int ni = 0; ni < 4; ni++) {
                    asm volatile(
                        "mma.sync.aligned.m16n8k16.row.col.f32.f16.f16.f32 "
                        "{%0,%1,%2,%3}, {%4,%5,%6,%7}, {%8,%9}, {%0,%1,%2,%3};"
                        : "+f"(acc[mi][ni][0]), "+f"(acc[mi][ni][1]),
                          "+f"(acc[mi][ni][2]), "+f"(acc[mi][ni][3])
                        : "r"(afrag[mi][0]), "r"(afrag[mi][1]),
                          "r"(afrag[mi][2]), "r"(afrag[mi][3]),
                          "r"(bfrag[ni][0]), "r"(bfrag[ni][1]));
                }
        }
        __syncthreads();
    }

#pragma unroll
    for (int mi = 0; mi < 4; mi++) {
        int r0 = rowBase + warp_m * 64 + mi * 16 + (lane >> 2);
#pragma unroll
        for (int ni = 0; ni < 4; ni++) {
            int col = warp_n * 32 + ni * 8 + (lane & 3) * 2;
            float b0 = __ldg(&bias[col]);
            float b1 = __ldg(&bias[col + 1]);
            if (r0 < N_NODES) {
                *(float2*)&out[r0 * D + col] =
                    make_float2(acc[mi][ni][0] + b0, acc[mi][ni][1] + b1);
            }
            if (r0 + 8 < N_NODES) {
                *(float2*)&out[(r0 + 8) * D + col] =
                    make_float2(acc[mi][ni][2] + b0, acc[mi][ni][3] + b1);
            }
        }
    }
}

// ---------------------------------------------------------------------------
extern "C" void kernel_launch(void* const* d_in, const int* in_sizes, int n_in,
                              void* d_out, int out_size) {
    const float* feat = (const float*)d_in[0];
    const int*   src  = (const int*)d_in[1];
    const int*   dst  = (const int*)d_in[2];
    const float* W    = (const float*)d_in[3];
    const float* bias = (const float*)d_in[4];
    float* out = (float*)d_out;

    const int E = in_sizes[1];

    __half* featH; cudaGetSymbolAddress((void**)&featH, g_featH);
    __half* h1H;   cudaGetSymbolAddress((void**)&h1H,   g_h1H);
    __half* h2H;   cudaGetSymbolAddress((void**)&h2H,   g_h2H);

    detect_idx_kernel<<<1, 32>>>(dst);

    // CSR build
    zero_deg_kernel<<<(N_NODES + 255) / 256, 256>>>();
    deg_kernel<<<(E + 255) / 256, 256>>>(dst, E);
    scan_phase1_kernel<<<SCAN_BLOCKS, 256>>>();
    scan_phase2_kernel<<<1, 512>>>();
    scan_phase3_kernel<<<SCAN_BLOCKS, 256>>>();
    csr_fill_kernel<<<(E + 255) / 256, 256>>>(src, dst, E);

    // feat -> fp16
    convert_feat_kernel<<<(N_NODES * D / 2 + 255) / 256, 256>>>(feat);

    // two SpMM hops (fp16 I/O)
    int gblocks = (N_NODES * 32 + 255) / 256;
    gather_kernel<<<gblocks, 256>>>(featH, h1H);
    gather_kernel<<<gblocks, 256>>>(h1H, h2H);

    // fused concat + linear on tensor cores
    int gemmBlocks = (N_NODES + 127) / 128;
    gemm_hmma_kernel<<<gemmBlocks, 256>>>(W, bias, out);
}